// round 17
// baseline (speedup 1.0000x reference)
#include <cuda_runtime.h>
#include <cuda_fp16.h>
#include <cuda_bf16.h>
#include <cstddef>
#include <cstdint>

#define BATCH 64
#define LSEQ 784
#define HDIM 512
#define NSTATE 64
#define NLAYERS 6
#define MT 7             // m-tiles of 128 rows, 7*128 = 896 >= 784
#define REV 895
#define KRRN 1024        // reversed-padded kernel length per h

// -------- scratch (no allocations allowed) --------
__device__ float g_h[(size_t)HDIM * LSEQ * BATCH];    // fp32 activations (last 2 LNs only)
__device__ __half g_z16[(size_t)HDIM * LSEQ * BATCH]; // z = h + conv(h), fp16 (H,L,B)
__device__ __half g_uf[(size_t)HDIM * LSEQ * BATCH];  // fp16 activations for gemm B operand
__device__ float g_K[NLAYERS * HDIM * LSEQ];          // conv kernels (fp32)
__device__ __half g_krh[(size_t)NLAYERS * HDIM * KRRN];  // K' reversed, fp16 hi
__device__ __half g_krl[(size_t)NLAYERS * HDIM * KRRN];  // K' reversed, fp16 lo
__device__ float g_wr[NLAYERS * HDIM * NSTATE];
__device__ float g_wi[NLAYERS * HDIM * NSTATE];
__device__ float g_cr[NLAYERS * HDIM * NSTATE];
__device__ float g_ci[NLAYERS * HDIM * NSTATE];
__device__ float g_xr[NLAYERS * HDIM * NSTATE];       // dt*Re(A)
__device__ float g_xi[NLAYERS * HDIM * NSTATE];       // dt*Im(A)
__device__ float g_pool[HDIM * BATCH];

// -------- ptx helpers --------
__device__ __forceinline__ uint32_t smaddr(const void* p) {
    return (uint32_t)__cvta_generic_to_shared(p);
}
__device__ __forceinline__ void ldsm4t(uint32_t& r0, uint32_t& r1, uint32_t& r2, uint32_t& r3,
                                       uint32_t addr) {
    asm volatile("ldmatrix.sync.aligned.m8n8.x4.trans.shared.b16 {%0,%1,%2,%3}, [%4];"
                 : "=r"(r0), "=r"(r1), "=r"(r2), "=r"(r3) : "r"(addr));
}
__device__ __forceinline__ void mma16816h(float* d, uint32_t a0, uint32_t a1, uint32_t a2,
                                          uint32_t a3, uint32_t b0, uint32_t b1) {
    asm volatile("mma.sync.aligned.m16n8k16.row.col.f32.f16.f16.f32 "
                 "{%0,%1,%2,%3}, {%4,%5,%6,%7}, {%8,%9}, {%0,%1,%2,%3};"
                 : "+f"(d[0]), "+f"(d[1]), "+f"(d[2]), "+f"(d[3])
                 : "r"(a0), "r"(a1), "r"(a2), "r"(a3), "r"(b0), "r"(b1));
}
__device__ __forceinline__ void cpasync16(uint32_t dst, const void* src, int sz) {
    asm volatile("cp.async.cg.shared.global [%0], [%1], 16, %2;"
                 :: "r"(dst), "l"(src), "r"(sz));
}

// -------- precompute discretized SSM params --------
__global__ void precompute_kernel(const float* __restrict__ log_dt,
                                  const float* __restrict__ log_A_real,
                                  const float* __restrict__ A_imag,
                                  const float* __restrict__ C_re,
                                  const float* __restrict__ C_im) {
    int idx = blockIdx.x * blockDim.x + threadIdx.x;
    if (idx >= NLAYERS * HDIM * NSTATE) return;
    int hh = (idx / NSTATE) % HDIM;
    int i = idx / (NSTATE * HDIM);
    float dt = expf(log_dt[i * HDIM + hh]);
    float Ar = -expf(log_A_real[idx]);
    float Ai = A_imag[idx];
    float xr = Ar * dt, xi = Ai * dt;
    float e = expf(xr);
    float wre = e * cosf(xi), wim = e * sinf(xi);
    float em1r = wre - 1.0f, em1i = wim;
    float Cre = C_re[idx], Cim = C_im[idx];
    float tr = Cre * em1r - Cim * em1i;
    float ti = Cre * em1i + Cim * em1r;
    float inv = 1.0f / (Ar * Ar + Ai * Ai);
    g_wr[idx] = wre; g_wi[idx] = wim;
    g_cr[idx] = (tr * Ar + ti * Ai) * inv;
    g_ci[idx] = (ti * Ar - tr * Ai) * inv;
    g_xr[idx] = xr; g_xi[idx] = xi;
}

// -------- kernel generation: state[l] = w^l, parallel over 7 l-chunks --------
// grid (HDIM/16, NLAYERS, 7), block 128. 8 lanes per h, 8 states per lane.
// Chunk start state w^{c0} computed exactly in double.
__global__ void __launch_bounds__(128) kgen_kernel() {
    __shared__ float shy[16][112];
    int tid = threadIdx.x;
    int warp = tid >> 5, lane = tid & 31;
    int g = lane >> 3, lg = lane & 7;
    int pairLocal = warp * 4 + g;
    int h = blockIdx.x * 16 + pairLocal;
    int layer = blockIdx.y;
    int c0 = blockIdx.z * 112;
    int pbase = (layer * HDIM + h) * NSTATE;
    float swr[8], swi[8], scr[8], sci[8], sre[8], sim[8];
#pragma unroll
    for (int j = 0; j < 8; j++) {
        int n = lg + 8 * j;
        swr[j] = g_wr[pbase + n]; swi[j] = g_wi[pbase + n];
        scr[j] = g_cr[pbase + n]; sci[j] = g_ci[pbase + n];
        // w^{c0} = exp(c0*xr) * (cos(c0*xi), sin(c0*xi)) in double
        double ar = (double)g_xr[pbase + n] * (double)c0;
        double ai = (double)g_xi[pbase + n] * (double)c0;
        double amp = exp(ar);
        sre[j] = (float)(amp * cos(ai));
        sim[j] = (float)(amp * sin(ai));
    }
    float* krow = g_K + (size_t)(layer * HDIM + h) * LSEQ + c0;
#pragma unroll 4
    for (int l = 0; l < 112; l++) {
        float acc = 0.0f;
#pragma unroll
        for (int j = 0; j < 8; j++) {
            acc = fmaf(scr[j], sre[j], acc);
            acc = fmaf(-sci[j], sim[j], acc);
            float nr = fmaf(swr[j], sre[j], -swi[j] * sim[j]);
            float ni = fmaf(swr[j], sim[j], swi[j] * sre[j]);
            sre[j] = nr; sim[j] = ni;
        }
        acc += __shfl_xor_sync(0xffffffffu, acc, 1, 8);
        acc += __shfl_xor_sync(0xffffffffu, acc, 2, 8);
        acc += __shfl_xor_sync(0xffffffffu, acc, 4, 8);
        if (lg == 0) shy[pairLocal][l] = 2.0f * acc;
    }
    __syncwarp();
#pragma unroll
    for (int k = 0; k < 14; k++)
        krow[lg + 8 * k] = shy[pairLocal][lg + 8 * k];
}

// -------- build reversed zero-padded fp16 hi/lo kernel, residual folded in --------
// KRR[t] = Kpad[REV - t]; K'[0] = K[0] + 1 + D  (so z = Sum K'[d] u[t-d] directly)
__global__ void __launch_bounds__(256) krr_kernel(const float* __restrict__ Dvec) {
    int h = blockIdx.x, layer = blockIdx.y;
    const float* kr = g_K + (size_t)(layer * HDIM + h) * LSEQ;
    __half* oh = g_krh + (size_t)(layer * HDIM + h) * KRRN;
    __half* ol = g_krl + (size_t)(layer * HDIM + h) * KRRN;
    float Dadd = 1.0f + Dvec[layer * HDIM + h];
    for (int t = threadIdx.x; t < KRRN; t += 256) {
        int d = REV - t;
        float v = (d >= 0 && d < LSEQ) ? kr[d] : 0.0f;
        if (d == 0) v += Dadd;
        __half hi = __float2half_rn(v);
        oh[t] = hi;
        ol[t] = __float2half_rn(v - __half2float(hi));
    }
}

// -------- encoder: fp16 activations only --------
__global__ void __launch_bounds__(256) encoder_kernel(const float* __restrict__ x,
                                                      const float* __restrict__ enc_w,
                                                      const float* __restrict__ enc_b) {
    int l = blockIdx.x;
    __shared__ float xs[BATCH];
    if (threadIdx.x < BATCH) xs[threadIdx.x] = x[threadIdx.x * LSEQ + l];
    __syncthreads();
    for (int idx = threadIdx.x; idx < HDIM * BATCH; idx += 256) {
        int h = idx >> 6, b = idx & 63;
        size_t off = ((size_t)h * LSEQ + l) * BATCH + b;
        float v = fmaf(xs[b], enc_w[h], enc_b[h]);
        g_uf[off] = __float2half_rn(v);
    }
}

// -------- S4 conv as triangular Toeplitz GEMM (fp16, K hi/lo split) --------
// 256 threads / 8 warps. Block: (h, 128-row m-tile). k-chunks of 64.
// Per k16 group: hoist 4 ldsm to fragment regs, issue 8 hi-mma then 8 lo-mma
// (accumulator RAW spacing 8). Triangular warp skip. z stored fp16 (half2).
__global__ void __launch_bounds__(256) gemm_kernel(int layer) {
    __shared__ __align__(16) __half Kraw[2][KRRN];             // 4KB
    __shared__ uint32_t Kpair[2][2][KRRN / 2];                 // 8KB [plane][shift][i]
    __shared__ __align__(16) uint8_t Usm[3][64 * 128];         // 24KB [buf]
    int tid = threadIdx.x;
    int id = blockIdx.x;
    int mt = MT - 1 - (id % MT);   // big-work-first scheduling
    int h = id / MT;
    int m0 = mt * 128;
    int warp = tid >> 5, lane = tid & 31;
    int g = lane >> 2, t2 = (lane & 3) * 2;

    {   // load kernel slice (hi+lo) vectorized: 2 planes x 1024 halves = 256 uint4
        const uint4* kh4 = (const uint4*)(g_krh + (size_t)(layer * HDIM + h) * KRRN);
        const uint4* kl4 = (const uint4*)(g_krl + (size_t)(layer * HDIM + h) * KRRN);
        int p = tid >> 7, j = tid & 127;
        ((uint4*)Kraw[p])[j] = p ? kl4[j] : kh4[j];
    }
    __syncthreads();
    {   // build dual-shift pair tables: Kpair[pl][sh][i] = elem(2i+sh) | elem(2i+sh+1)<<16
        const uint16_t* r0 = (const uint16_t*)Kraw[0];
        const uint16_t* r1 = (const uint16_t*)Kraw[1];
#pragma unroll
        for (int e = tid; e < 2048; e += 256) {
            int pl = e >> 10, rest = e & 1023;
            int sh = rest >> 9, i = rest & 511;
            int x = 2 * i + sh;
            const uint16_t* rr = pl ? r1 : r0;
            uint32_t lo = rr[x];
            uint32_t hi = (x + 1 < KRRN) ? rr[x + 1] : 0u;
            Kpair[pl][sh][i] = lo | (hi << 16);
        }
    }

    // staging: 256 threads, two 16B cp.async per 64-row chunk (rows sk, sk+32)
    const __half* usrc = g_uf + (size_t)h * (LSEQ * BATCH);
    int sk = tid >> 3, sj = tid & 7;             // sk 0..31; second row = sk+32
    uint32_t doffA = (uint32_t)(sk * 128 + ((sj ^ (sk & 7)) << 4));
    uint32_t doffB = (uint32_t)((sk + 32) * 128 + ((sj ^ ((sk + 32) & 7)) << 4));
    uint32_t sb0 = smaddr(&Usm[0][0]), sb1 = smaddr(&Usm[1][0]), sb2 = smaddr(&Usm[2][0]);

    int nc = mt * 2 + 2;   // 64-wide chunks cover k < m0+128

    // prologue: issue chunks 0 and 1 (chunk 0 rows always < 784)
    cpasync16(sb0 + doffA, usrc + (size_t)sk * BATCH + sj * 8, 16);
    cpasync16(sb0 + doffB, usrc + (size_t)(sk + 32) * BATCH + sj * 8, 16);
    asm volatile("cp.async.commit_group;");
    {
        int kA = 64 + sk, kB = 64 + sk + 32;
        cpasync16(sb1 + doffA, usrc + (size_t)(kA < LSEQ ? kA : 0) * BATCH + sj * 8,
                  (kA < LSEQ) ? 16 : 0);
        cpasync16(sb1 + doffB, usrc + (size_t)(kB < LSEQ ? kB : 0) * BATCH + sj * 8,
                  (kB < LSEQ) ? 16 : 0);
        asm volatile("cp.async.commit_group;");
    }
    __syncthreads();   // Kpair tables ready before mma loop

    float acc[8][4];
#pragma unroll
    for (int u = 0; u < 8; u++)
#pragma unroll
        for (int c = 0; c < 4; c++) acc[u][c] = 0.0f;

    // ldmatrix.trans lane mapping
    int r = lane & 7, mm = lane >> 3;
    int khh = mm & 1, bg = mm >> 1;
    uint32_t rowoff = (uint32_t)((khh * 8 + r) * 128);

    // A-fragment index base; parity of x is constant per lane across the loop
    int xb = REV - m0 - warp * 16 + t2 - g;
    int par = xb & 1;
    const uint32_t* KPh = Kpair[0][par];
    const uint32_t* KPl = Kpair[1][par];
    int wmax = m0 + warp * 16 + 15;   // triangular skip bound for this warp

    uint32_t sbase[3] = { sb0, sb1, sb2 };
    int buf = 0;
    for (int kc = 0; kc < nc; kc++) {
        asm volatile("cp.async.wait_group 1;" ::: "memory");
        __syncthreads();
        {   // issue chunk kc+2 into the buffer freed by chunk kc-1
            if (kc + 2 < nc) {
                int nb = buf + 2; if (nb >= 3) nb -= 3;
                int kA = (kc + 2) * 64 + sk, kB = kA + 32;
                cpasync16(sbase[nb] + doffA,
                          usrc + (size_t)(kA < LSEQ ? kA : 0) * BATCH + sj * 8,
                          (kA < LSEQ) ? 16 : 0);
                cpasync16(sbase[nb] + doffB,
                          usrc + (size_t)(kB < LSEQ ? kB : 0) * BATCH + sj * 8,
                          (kB < LSEQ) ? 16 : 0);
            }
            asm volatile("cp.async.commit_group;");   // empty group ok at tail
        }
        uint32_t bb = sbase[buf] + rowoff;
#pragma unroll
        for (int kk = 0; kk < 64; kk += 16) {
            int kabs = kc * 64 + kk;
            if (kabs > wmax) break;                  // A all-zero above the diagonal
            int xi = (xb + kabs) >> 1;               // pair index (parity folded into KP*)
            uint32_t ah0 = KPh[xi], ah1 = KPh[xi - 4], ah2 = KPh[xi + 4];
            uint32_t al0 = KPl[xi], al1 = KPl[xi - 4], al2 = KPl[xi + 4];
            uint32_t kof = (uint32_t)(kk * 128);
            uint32_t rf[4][4];
#pragma unroll
            for (int ng = 0; ng < 4; ng++) {
                uint32_t unit = (uint32_t)(((ng * 2 + bg) ^ r) << 4);
                ldsm4t(rf[ng][0], rf[ng][1], rf[ng][2], rf[ng][3], bb + kof + unit);
            }
#pragma unroll
            for (int ng = 0; ng < 4; ng++) {         // all hi-mma first
                mma16816h(acc[2 * ng],     ah0, ah1, ah2, ah0, rf[ng][0], rf[ng][1]);
                mma16816h(acc[2 * ng + 1], ah0, ah1, ah2, ah0, rf[ng][2], rf[ng][3]);
            }
#pragma unroll
            for (int ng = 0; ng < 4; ng++) {         // then all lo-mma (RAW spacing 8)
                mma16816h(acc[2 * ng],     al0, al1, al2, al0, rf[ng][0], rf[ng][1]);
                mma16816h(acc[2 * ng + 1], al0, al1, al2, al0, rf[ng][2], rf[ng][3]);
            }
        }
        buf++; if (buf == 3) buf = 0;
    }

    // epilogue: z = acc (residual + D folded into K'), fp16 half2 into g_z16 (H,L,B)
    __half* Z = g_z16 + (size_t)h * (LSEQ * BATCH);
    int R0 = m0 + warp * 16 + g;
    int R1 = R0 + 8;
#pragma unroll
    for (int u = 0; u < 8; u++) {
        int b = u * 8 + t2;
        if (R0 < LSEQ) {
            size_t o = (size_t)R0 * BATCH + b;
            *(__half2*)(Z + o) = __floats2half2_rn(acc[u][0], acc[u][1]);
        }
        if (R1 < LSEQ) {
            size_t o = (size_t)R1 * BATCH + b;
            *(__half2*)(Z + o) = __floats2half2_rn(acc[u][2], acc[u][3]);
        }
    }
}

// -------- layernorm over H, (H,L,B) layout, coalesced two-pass --------
// addY=1: read z from g_z16 (fp16); addY=0: read g_h (fp32).
__global__ void __launch_bounds__(512) ln_kernel(const float* __restrict__ gamma,
                                                 const float* __restrict__ beta,
                                                 int addY, int writeFP, int writeHF) {
    int l = blockIdx.x;
    int t = threadIdx.x;
    int b = t & 63, hp = t >> 6;   // hp 0..7
    const __half* srcH = g_z16 + (size_t)l * BATCH;
    const float* srcF = g_h + (size_t)l * BATCH;
    float s1 = 0.0f, s2 = 0.0f;
    for (int h = hp; h < HDIM; h += 8) {
        float v = addY ? __half2float(__ldg(srcH + (size_t)h * (LSEQ * BATCH) + b))
                       : __ldg(srcF + (size_t)h * (LSEQ * BATCH) + b);
        s1 += v; s2 += v * v;
    }
    __shared__ float r1[8][64], r2[8][64];
    __shared__ float smean[64], srstd[64];
    r1[hp][b] = s1; r2[hp][b] = s2;
    __syncthreads();
    if (t < 64) {
        float a1 = 0.0f, a2 = 0.0f;
#pragma unroll
        for (int i = 0; i < 8; i++) { a1 += r1[i][t]; a2 += r2[i][t]; }
        float mean = a1 * (1.0f / HDIM);
        float var = a2 * (1.0f / HDIM) - mean * mean;
        smean[t] = mean;
        srstd[t] = rsqrtf(var + 1e-5f);
    }
    __syncthreads();
    float mean = smean[b], rstd = srstd[b];
    size_t lb = (size_t)l * BATCH;
    for (int h = hp; h < HDIM; h += 8) {
        size_t off = (size_t)h * (LSEQ * BATCH) + lb + b;
        float v = addY ? __half2float(__ldg(srcH + (size_t)h * (LSEQ * BATCH) + b))
                       : __ldg(srcF + (size_t)h * (LSEQ * BATCH) + b);
        v = (v - mean) * rstd * gamma[h] + beta[h];
        if (writeFP) g_h[off] = v;
        if (writeHF) g_uf[off] = __float2half_rn(v);
    }
}

// -------- mean-pool over L --------
__global__ void __launch_bounds__(256) pool_kernel() {
    int h = blockIdx.x;
    int b = threadIdx.x & 63, part = threadIdx.x >> 6;
    float s = 0.0f;
    for (int l = part; l < LSEQ; l += 4)
        s += g_h[((size_t)h * LSEQ + l) * BATCH + b];
    __shared__ float red[4][64];
    red[part][b] = s;
    __syncthreads();
    if (part == 0)
        g_pool[h * BATCH + b] = (red[0][b] + red[1][b] + red[2][b] + red[3][b]) * (1.0f / LSEQ);
}

// -------- decode to 10 classes --------
__global__ void __launch_bounds__(256) decode_kernel(const float* __restrict__ dec_w,
                                                     const float* __restrict__ dec_b,
                                                     float* __restrict__ out) {
    int b = blockIdx.x;
    int t = threadIdx.x;
    float acc[10];
#pragma unroll
    for (int k = 0; k < 10; k++) acc[k] = 0.0f;
    for (int h = t; h < HDIM; h += 256) {
        float p = g_pool[h * BATCH + b];
#pragma unroll
        for (int k = 0; k < 10; k++) acc[k] = fmaf(p, dec_w[h * 10 + k], acc[k]);
    }
    __shared__ float red[256];
    for (int k = 0; k < 10; k++) {
        red[t] = acc[k];
        __syncthreads();
        for (int st = 128; st >= 1; st >>= 1) {
            if (t < st) red[t] += red[t + st];
            __syncthreads();
        }
        if (t == 0) out[b * 10 + k] = red[0] + dec_b[k];
        __syncthreads();
    }
}

extern "C" void kernel_launch(void* const* d_in, const int* in_sizes, int n_in,
                              void* d_out, int out_size) {
    const float* x          = (const float*)d_in[0];
    const float* enc_w      = (const float*)d_in[1];
    const float* enc_b      = (const float*)d_in[2];
    const float* log_dt     = (const float*)d_in[3];
    const float* log_A_real = (const float*)d_in[4];
    const float* A_imag     = (const float*)d_in[5];
    const float* C_re       = (const float*)d_in[6];
    const float* C_im       = (const float*)d_in[7];
    const float* Dvec       = (const float*)d_in[8];
    const float* ln_g       = (const float*)d_in[9];
    const float* ln_b       = (const float*)d_in[10];
    const float* fn_g       = (const float*)d_in[11];
    const float* fn_b       = (const float*)d_in[12];
    const float* dec_w      = (const float*)d_in[13];
    const float* dec_b      = (const float*)d_in[14];
    float* out = (float*)d_out;

    int np = NLAYERS * HDIM * NSTATE;
    precompute_kernel<<<(np + 255) / 256, 256>>>(log_dt, log_A_real, A_imag, C_re, C_im);
    kgen_kernel<<<dim3(HDIM / 16, NLAYERS, 7), 128>>>();
    krr_kernel<<<dim3(HDIM, NLAYERS), 256>>>(Dvec);
    encoder_kernel<<<LSEQ, 256>>>(x, enc_w, enc_b);

    for (int i = 0; i < NLAYERS; i++) {
        gemm_kernel<<<HDIM * MT, 256>>>(i);
        int last = (i == NLAYERS - 1);
        ln_kernel<<<LSEQ, 512>>>(ln_g + i * HDIM, ln_b + i * HDIM, 1, last, !last);
    }
    ln_kernel<<<LSEQ, 512>>>(fn_g, fn_b, 0, 1, 0);
    pool_kernel<<<HDIM, 256>>>();
    decode_kernel<<<BATCH, 256>>>(dec_w, dec_b, out);
}